// round 9
// baseline (speedup 1.0000x reference)
#include <cuda_runtime.h>
#include <cuda_bf16.h>
#include <cstdint>

// Problem shape (fixed)
#define B   64
#define C   64
#define NQ  32
#define S   1024
#define KD  128          // embedding dim
#define MT  128          // Q rows per block (4 b's * 32 n)
#define NT  128          // doc tokens per s-tile
#define NSPLIT 2         // s-range split (wave-quantization fix)
#define TPC (S / NT / NSPLIT)   // tiles per CTA = 4
#define PADB 136         // smem row stride in bf16 elems
#define TEMP_INV 50.0f

__device__ float g_scores[B * C];
__device__ float g_pmax[NSPLIT * B * C * NQ];   // per-(shalf,b,c,n) partial maxes, 1 MB
__device__ __nv_bfloat16 g_qbf[B * NQ * KD];    // 0.5 MB
__device__ __nv_bfloat16 g_dbf[C * S * KD];     // 16 MB

__device__ __forceinline__ uint32_t s2u(const void* p) {
    return (uint32_t)__cvta_generic_to_shared(p);
}
__device__ __forceinline__ void cp_async16(void* dst, const void* src) {
    asm volatile("cp.async.cg.shared.global [%0], [%1], 16;\n"
                 :: "r"(s2u(dst)), "l"(src));
}
__device__ __forceinline__ uint32_t pack_bf16x2(float lo, float hi) {
    __nv_bfloat162 h = __floats2bfloat162_rn(lo, hi);
    return *reinterpret_cast<uint32_t*>(&h);
}

// ---------------------------------------------------------------------------
// Kernel 0: fp32 -> bf16 conversion (one-time, DRAM-bound)
// ---------------------------------------------------------------------------
__global__ void convert_bf16_kernel(const float* __restrict__ q,
                                    const float* __restrict__ d)
{
    const size_t nq4 = (size_t)B * NQ * KD / 4;        // 65536
    const size_t nd4 = (size_t)C * S  * KD / 4;        // 2097152
    const size_t stride = (size_t)gridDim.x * blockDim.x;
    const size_t t0 = (size_t)blockIdx.x * blockDim.x + threadIdx.x;
    for (size_t idx = t0; idx < nq4; idx += stride) {
        float4 v = reinterpret_cast<const float4*>(q)[idx];
        uint2 o; o.x = pack_bf16x2(v.x, v.y); o.y = pack_bf16x2(v.z, v.w);
        reinterpret_cast<uint2*>(g_qbf)[idx] = o;
    }
    for (size_t idx = t0; idx < nd4; idx += stride) {
        float4 v = reinterpret_cast<const float4*>(d)[idx];
        uint2 o; o.x = pack_bf16x2(v.x, v.y); o.y = pack_bf16x2(v.z, v.w);
        reinterpret_cast<uint2*>(g_dbf)[idx] = o;
    }
}

// ---------------------------------------------------------------------------
// Kernel 1: bf16 mma.sync m16n8k16 GEMM, fused max epilogue.
// Block (mtile, shalf, c): 128 Q-rows x 512 doc tokens (4 s-tiles).
// 4 warps, warp grid 2x2, warp tile 64x64. Double-buffered cp.async on D.
// 2 CTAs/SM. Writes per-(b,n) partial maxes (no atomics).
// ---------------------------------------------------------------------------
__global__ __launch_bounds__(128, 2)
void colbert_scores_mma(void)
{
    extern __shared__ __nv_bfloat16 shb[];
    __nv_bfloat16* qs = shb;                    // MT * PADB
    __nv_bfloat16* ds = shb + MT * PADB;        // 2 * NT * PADB (double buffer)

    const int mtile = blockIdx.x >> 1;  // 0..15
    const int shalf = blockIdx.x & 1;   // 0..1
    const int c     = blockIdx.y;       // 0..63
    const int tid   = threadIdx.x;
    const int wid   = tid >> 5;         // 0..3
    const int lane  = tid & 31;
    const int warp_m = wid >> 1;        // 0..1
    const int warp_n = wid & 1;         // 0..1
    const int gID   = lane >> 2;
    const int tig   = lane & 3;

    const __nv_bfloat16* __restrict__ qbase = g_qbf + (size_t)mtile * MT * KD;
    const __nv_bfloat16* __restrict__ dbase =
        g_dbf + (size_t)c * S * KD + (size_t)shalf * TPC * NT * KD;

    // ---- load Q tile (once): 2048 x 16B chunks, 16 per thread ----
    #pragma unroll
    for (int i = 0; i < 16; i++) {
        int idx = i * 128 + tid;
        int row = idx >> 4;
        int c8  = idx & 15;
        cp_async16(&qs[row * PADB + c8 * 8], qbase + (size_t)row * KD + c8 * 8);
    }
    // ---- prefetch D s-tile 0 ----
    #pragma unroll
    for (int i = 0; i < 16; i++) {
        int idx = i * 128 + tid;
        int row = idx >> 4;
        int c8  = idx & 15;
        cp_async16(&ds[row * PADB + c8 * 8], dbase + (size_t)row * KD + c8 * 8);
    }
    asm volatile("cp.async.commit_group;\n");

    float runmax[4][2];
    #pragma unroll
    for (int mt = 0; mt < 4; mt++)
        #pragma unroll
        for (int h = 0; h < 2; h++)
            runmax[mt][h] = __int_as_float(0xff800000);

    for (int t = 0; t < TPC; t++) {
        if (t < TPC - 1) {
            __nv_bfloat16* dst = ds + ((t + 1) & 1) * NT * PADB;
            const __nv_bfloat16* src = dbase + (size_t)(t + 1) * NT * KD;
            #pragma unroll
            for (int i = 0; i < 16; i++) {
                int idx = i * 128 + tid;
                int row = idx >> 4;
                int c8  = idx & 15;
                cp_async16(&dst[row * PADB + c8 * 8], src + (size_t)row * KD + c8 * 8);
            }
            asm volatile("cp.async.commit_group;\n");
            asm volatile("cp.async.wait_group 1;\n");
        } else {
            asm volatile("cp.async.wait_group 0;\n");
        }
        __syncthreads();   // tile t (and Q on t=0) visible to all warps

        const __nv_bfloat16* db = ds + (t & 1) * NT * PADB;

        float acc[4][8][4];
        #pragma unroll
        for (int mt = 0; mt < 4; mt++)
            #pragma unroll
            for (int nt = 0; nt < 8; nt++)
                #pragma unroll
                for (int r = 0; r < 4; r++) acc[mt][nt][r] = 0.0f;

        const int arow = warp_m * 64 + gID;
        const int brow = warp_n * 64 + gID;

        #pragma unroll
        for (int ks = 0; ks < 8; ks++) {
            const int k0 = ks * 16;
            uint32_t a[4][4];
            #pragma unroll
            for (int mt = 0; mt < 4; mt++) {
                const __nv_bfloat16* ap =
                    &qs[(arow + mt * 16) * PADB + k0 + 2 * tig];
                a[mt][0] = *reinterpret_cast<const uint32_t*>(ap);
                a[mt][1] = *reinterpret_cast<const uint32_t*>(ap + 8 * PADB);
                a[mt][2] = *reinterpret_cast<const uint32_t*>(ap + 8);
                a[mt][3] = *reinterpret_cast<const uint32_t*>(ap + 8 * PADB + 8);
            }
            uint32_t bf[8][2];
            #pragma unroll
            for (int nt = 0; nt < 8; nt++) {
                const __nv_bfloat16* bp =
                    &db[(brow + nt * 8) * PADB + k0 + 2 * tig];
                bf[nt][0] = *reinterpret_cast<const uint32_t*>(bp);
                bf[nt][1] = *reinterpret_cast<const uint32_t*>(bp + 8);
            }
            #pragma unroll
            for (int mt = 0; mt < 4; mt++)
                #pragma unroll
                for (int nt = 0; nt < 8; nt++) {
                    asm volatile(
                        "mma.sync.aligned.m16n8k16.row.col.f32.bf16.bf16.f32 "
                        "{%0,%1,%2,%3}, {%4,%5,%6,%7}, {%8,%9}, {%0,%1,%2,%3};\n"
                        : "+f"(acc[mt][nt][0]), "+f"(acc[mt][nt][1]),
                          "+f"(acc[mt][nt][2]), "+f"(acc[mt][nt][3])
                        : "r"(a[mt][0]), "r"(a[mt][1]), "r"(a[mt][2]), "r"(a[mt][3]),
                          "r"(bf[nt][0]), "r"(bf[nt][1]));
                }
        }

        // c0,c1 -> row gID; c2,c3 -> row gID+8. Cols irrelevant (max over s).
        #pragma unroll
        for (int mt = 0; mt < 4; mt++) {
            float m0 = __int_as_float(0xff800000);
            float m1 = __int_as_float(0xff800000);
            #pragma unroll
            for (int nt = 0; nt < 8; nt++) {
                m0 = fmaxf(m0, fmaxf(acc[mt][nt][0], acc[mt][nt][1]));
                m1 = fmaxf(m1, fmaxf(acc[mt][nt][2], acc[mt][nt][3]));
            }
            runmax[mt][0] = fmaxf(runmax[mt][0], m0);
            runmax[mt][1] = fmaxf(runmax[mt][1], m1);
        }
        __syncthreads();   // buffer reads done before next prefetch overwrites
    }

    // ---- reduce: quad max across tig, publish per (warp_n, row) ----
    float* red = reinterpret_cast<float*>(shb);   // reuse smem: 2*128 floats
    #pragma unroll
    for (int mt = 0; mt < 4; mt++)
        #pragma unroll
        for (int h = 0; h < 2; h++) {
            float m = runmax[mt][h];
            m = fmaxf(m, __shfl_xor_sync(0xffffffffu, m, 1));
            m = fmaxf(m, __shfl_xor_sync(0xffffffffu, m, 2));
            if (tig == 0) {
                int row = warp_m * 64 + mt * 16 + h * 8 + gID;
                red[warp_n * 128 + row] = m;
            }
        }
    __syncthreads();

    // ---- write partial max: row -> (b = mtile*4 + row/32, n = row%32) ----
    {
        int row = tid;                     // 0..127
        float v = fmaxf(red[row], red[128 + row]);
        int b = mtile * 4 + (row >> 5);
        int n = row & 31;
        g_pmax[(((size_t)shalf * B + b) * C + c) * NQ + n] = v;
    }
}

// ---------------------------------------------------------------------------
// Kernel 1b: combine partial maxes -> scores[b][c] = sum_n max(p0, p1)
// ---------------------------------------------------------------------------
__global__ void colbert_combine_kernel(void)
{
    const int b = blockIdx.x;      // 0..63
    const int c = threadIdx.x;     // 0..63
    const size_t base = ((size_t)b * C + c) * NQ;
    const size_t half = (size_t)B * C * NQ;
    const float4* p0 = reinterpret_cast<const float4*>(g_pmax + base);
    const float4* p1 = reinterpret_cast<const float4*>(g_pmax + half + base);
    float ssum = 0.0f;
    #pragma unroll
    for (int i = 0; i < NQ / 4; i++) {
        float4 a = p0[i], d = p1[i];
        ssum += fmaxf(a.x, d.x) + fmaxf(a.y, d.y)
              + fmaxf(a.z, d.z) + fmaxf(a.w, d.w);
    }
    g_scores[b * C + c] = ssum;
}

// ---------------------------------------------------------------------------
// Kernel 2: normalize, log-softmax, NLL mean. Warp-parallel: 16 warps x 4 rows.
// ---------------------------------------------------------------------------
__global__ void colbert_loss_kernel(const float* __restrict__ q,
                                    const int*   __restrict__ offset_p,
                                    float*       __restrict__ out)
{
    __shared__ float losses[B];
    const int tid  = threadIdx.x;
    const int wid  = tid >> 5;
    const int lane = tid & 31;
    const int label_off = offset_p[0];

    #pragma unroll
    for (int r = 0; r < 4; r++) {
        const int b = wid * 4 + r;
        unsigned bal = __ballot_sync(0xffffffffu,
                          q[(size_t)b * NQ * KD + (size_t)lane * KD] != 0.0f);
        const float inv = TEMP_INV / (float)__popc(bal);

        float l0 = g_scores[b * C + lane]      * inv;
        float l1 = g_scores[b * C + 32 + lane] * inv;

        float mx = fmaxf(l0, l1);
        #pragma unroll
        for (int o = 16; o > 0; o >>= 1)
            mx = fmaxf(mx, __shfl_xor_sync(0xffffffffu, mx, o));

        float se = expf(l0 - mx) + expf(l1 - mx);
        #pragma unroll
        for (int o = 16; o > 0; o >>= 1)
            se += __shfl_xor_sync(0xffffffffu, se, o);

        const int label = b + label_off;
        const float ll = (label < 32)
                       ? __shfl_sync(0xffffffffu, l0, label)
                       : __shfl_sync(0xffffffffu, l1, label - 32);
        if (lane == 0)
            losses[b] = -(ll - mx - logf(se));
    }
    __syncthreads();

    if (tid < 32) {
        float v = losses[tid] + losses[tid + 32];
        #pragma unroll
        for (int o = 16; o > 0; o >>= 1)
            v += __shfl_xor_sync(0xffffffffu, v, o);
        if (tid == 0) out[0] = v / (float)B;
    }
}

// ---------------------------------------------------------------------------
extern "C" void kernel_launch(void* const* d_in, const int* in_sizes, int n_in,
                              void* d_out, int out_size)
{
    const float* q   = (const float*)d_in[0];
    const float* d   = (const float*)d_in[1];
    const int*   off = (const int*)  d_in[2];
    float*       out = (float*)d_out;

    const size_t smem_bytes = (size_t)(MT * PADB + 2 * NT * PADB)
                              * sizeof(__nv_bfloat16);   // 104448

    cudaFuncSetAttribute(colbert_scores_mma,
                         cudaFuncAttributeMaxDynamicSharedMemorySize,
                         (int)smem_bytes);

    convert_bf16_kernel<<<1024, 256>>>(q, d);
    dim3 grid(16 * NSPLIT, C);   // (mtile, shalf) x c = 2048 CTAs
    colbert_scores_mma<<<grid, 128, smem_bytes>>>();
    colbert_combine_kernel<<<B, C>>>();
    colbert_loss_kernel<<<1, 512>>>(q, off, out);
}

// round 10
// speedup vs baseline: 1.1271x; 1.1271x over previous
#include <cuda_runtime.h>
#include <cuda_bf16.h>
#include <cstdint>

// Problem shape (fixed)
#define B   64
#define C   64
#define NQ  32
#define S   1024
#define KD  128          // embedding dim
#define MT  128          // Q rows per block (4 b's * 32 n)
#define NT  128          // doc tokens per s-tile
#define PADB 136         // smem row stride in bf16 elems (272 B -> bank+4 per row)
#define TEMP_INV 50.0f

__device__ float g_scores[B * C];
__device__ float g_inv[B];                      // TEMP_INV / len(b), from convert kernel
__device__ __nv_bfloat16 g_qbf[B * NQ * KD];    // 0.5 MB
__device__ __nv_bfloat16 g_dbf[C * S * KD];     // 16 MB

__device__ __forceinline__ uint32_t s2u(const void* p) {
    return (uint32_t)__cvta_generic_to_shared(p);
}
__device__ __forceinline__ void cp_async16(uint32_t dst, const void* src) {
    asm volatile("cp.async.cg.shared.global [%0], [%1], 16;\n"
                 :: "r"(dst), "l"(src));
}
__device__ __forceinline__ uint32_t pack_bf16x2(float lo, float hi) {
    __nv_bfloat162 h = __floats2bfloat162_rn(lo, hi);
    return *reinterpret_cast<uint32_t*>(&h);
}
__device__ __forceinline__ void ldsm_x4(uint32_t addr, uint32_t& r0, uint32_t& r1,
                                        uint32_t& r2, uint32_t& r3) {
    asm volatile("ldmatrix.sync.aligned.m8n8.x4.shared.b16 {%0,%1,%2,%3}, [%4];"
                 : "=r"(r0), "=r"(r1), "=r"(r2), "=r"(r3) : "r"(addr));
}

// ---------------------------------------------------------------------------
// Kernel 0: fp32 -> bf16 conversion + per-b length precompute (one-time)
// ---------------------------------------------------------------------------
__global__ void convert_bf16_kernel(const float* __restrict__ q,
                                    const float* __restrict__ d)
{
    // block 0, threads 0..63: lengths (overlaps with conversion on other blocks)
    if (blockIdx.x == 0 && threadIdx.x < B) {
        const int b = threadIdx.x;
        int len = 0;
        #pragma unroll
        for (int n = 0; n < NQ; n++)
            len += (q[(size_t)b * NQ * KD + (size_t)n * KD] != 0.0f) ? 1 : 0;
        g_inv[b] = TEMP_INV / (float)len;
    }

    const size_t nq4 = (size_t)B * NQ * KD / 4;        // 65536
    const size_t nd4 = (size_t)C * S  * KD / 4;        // 2097152
    const size_t stride = (size_t)gridDim.x * blockDim.x;
    const size_t t0 = (size_t)blockIdx.x * blockDim.x + threadIdx.x;
    for (size_t idx = t0; idx < nq4; idx += stride) {
        float4 v = reinterpret_cast<const float4*>(q)[idx];
        uint2 o; o.x = pack_bf16x2(v.x, v.y); o.y = pack_bf16x2(v.z, v.w);
        reinterpret_cast<uint2*>(g_qbf)[idx] = o;
    }
    for (size_t idx = t0; idx < nd4; idx += stride) {
        float4 v = reinterpret_cast<const float4*>(d)[idx];
        uint2 o; o.x = pack_bf16x2(v.x, v.y); o.y = pack_bf16x2(v.z, v.w);
        reinterpret_cast<uint2*>(g_dbf)[idx] = o;
    }
}

// ---------------------------------------------------------------------------
// Kernel 1: bf16 mma.sync m16n8k16 GEMM, fused max/sum epilogue.
// Block (mtile, c): 128 Q-rows x all 1024 tokens of doc c (8 s-tiles).
// 4 warps, 2x2 grid, warp tile 64x64. ldmatrix.x4 fragment loads
// (8 LDSM vs 32 LDS.32 per ks per warp). Double-buffered cp.async. 2 CTAs/SM.
// ---------------------------------------------------------------------------
__global__ __launch_bounds__(128, 2)
void colbert_scores_mma(void)
{
    extern __shared__ __nv_bfloat16 shb[];
    const uint32_t qs_u = s2u(shb);
    const uint32_t ds_u = qs_u + MT * PADB * 2;        // D double buffer base

    const int mtile = blockIdx.x;       // 0..15
    const int c     = blockIdx.y;       // 0..63
    const int tid   = threadIdx.x;
    const int wid   = tid >> 5;         // 0..3
    const int lane  = tid & 31;
    const int warp_m = wid >> 1;        // 0..1
    const int warp_n = wid & 1;         // 0..1
    const int gID   = lane >> 2;
    const int tig   = lane & 3;

    const __nv_bfloat16* __restrict__ qbase = g_qbf + (size_t)mtile * MT * KD;
    const __nv_bfloat16* __restrict__ dbase = g_dbf + (size_t)c * S * KD;

    // ---- load Q tile (once): 2048 x 16B chunks, 16 per thread ----
    #pragma unroll
    for (int i = 0; i < 16; i++) {
        int idx = i * 128 + tid;
        int row = idx >> 4;
        int c8  = idx & 15;
        cp_async16(qs_u + (row * PADB + c8 * 8) * 2, qbase + (size_t)row * KD + c8 * 8);
    }
    // ---- prefetch D s-tile 0 ----
    #pragma unroll
    for (int i = 0; i < 16; i++) {
        int idx = i * 128 + tid;
        int row = idx >> 4;
        int c8  = idx & 15;
        cp_async16(ds_u + (row * PADB + c8 * 8) * 2, dbase + (size_t)row * KD + c8 * 8);
    }
    asm volatile("cp.async.commit_group;\n");

    // ---- ldmatrix per-lane base addresses (bytes) ----
    // A (x4 per mt): matrices (m0-7,k0),(m8-15,k0),(m0-7,k8),(m8-15,k8)
    //   lane L: row = ((L>>3)&1)*8 + (L&7), col = 8*(L>>4)
    // B (x4 per np, covers nt=2np,2np+1):
    //   matrices (n(2np),k0),(n(2np),k8),(n(2np+1),k0),(n(2np+1),k8)
    //   lane L: row = ((L>>4)&1)*8 + (L&7), col = 8*((L>>3)&1)
    uint32_t a_base[4], b_base[4];
    {
        const int arow_l = ((lane >> 3) & 1) * 8 + (lane & 7);
        const int acol_l = 8 * (lane >> 4);
        #pragma unroll
        for (int mt = 0; mt < 4; mt++)
            a_base[mt] = qs_u +
                ((warp_m * 64 + mt * 16 + arow_l) * PADB + acol_l) * 2;
        const int brow_l = ((lane >> 4) & 1) * 8 + (lane & 7);
        const int bcol_l = 8 * ((lane >> 3) & 1);
        #pragma unroll
        for (int np = 0; np < 4; np++)
            b_base[np] = ds_u +
                ((warp_n * 64 + np * 16 + brow_l) * PADB + bcol_l) * 2;
    }

    float runmax[4][2];
    #pragma unroll
    for (int mt = 0; mt < 4; mt++)
        #pragma unroll
        for (int h = 0; h < 2; h++)
            runmax[mt][h] = __int_as_float(0xff800000);

    for (int t = 0; t < S / NT; t++) {
        if (t < S / NT - 1) {
            uint32_t dst = ds_u + ((t + 1) & 1) * NT * PADB * 2;
            const __nv_bfloat16* src = dbase + (size_t)(t + 1) * NT * KD;
            #pragma unroll
            for (int i = 0; i < 16; i++) {
                int idx = i * 128 + tid;
                int row = idx >> 4;
                int c8  = idx & 15;
                cp_async16(dst + (row * PADB + c8 * 8) * 2,
                           src + (size_t)row * KD + c8 * 8);
            }
            asm volatile("cp.async.commit_group;\n");
            asm volatile("cp.async.wait_group 1;\n");
        } else {
            asm volatile("cp.async.wait_group 0;\n");
        }
        __syncthreads();   // tile t (and Q on t=0) visible to all warps

        const uint32_t bufoff = (t & 1) * NT * PADB * 2;

        float acc[4][8][4];
        #pragma unroll
        for (int mt = 0; mt < 4; mt++)
            #pragma unroll
            for (int nt = 0; nt < 8; nt++)
                #pragma unroll
                for (int r = 0; r < 4; r++) acc[mt][nt][r] = 0.0f;

        #pragma unroll
        for (int ks = 0; ks < 8; ks++) {
            const uint32_t koff = ks * 32;          // 16 bf16 = 32 bytes
            uint32_t a[4][4];
            #pragma unroll
            for (int mt = 0; mt < 4; mt++)
                ldsm_x4(a_base[mt] + koff,
                        a[mt][0], a[mt][1], a[mt][2], a[mt][3]);
            uint32_t bf[8][2];
            #pragma unroll
            for (int np = 0; np < 4; np++)
                ldsm_x4(b_base[np] + bufoff + koff,
                        bf[2*np][0], bf[2*np][1], bf[2*np+1][0], bf[2*np+1][1]);
            #pragma unroll
            for (int mt = 0; mt < 4; mt++)
                #pragma unroll
                for (int nt = 0; nt < 8; nt++) {
                    asm volatile(
                        "mma.sync.aligned.m16n8k16.row.col.f32.bf16.bf16.f32 "
                        "{%0,%1,%2,%3}, {%4,%5,%6,%7}, {%8,%9}, {%0,%1,%2,%3};\n"
                        : "+f"(acc[mt][nt][0]), "+f"(acc[mt][nt][1]),
                          "+f"(acc[mt][nt][2]), "+f"(acc[mt][nt][3])
                        : "r"(a[mt][0]), "r"(a[mt][1]), "r"(a[mt][2]), "r"(a[mt][3]),
                          "r"(bf[nt][0]), "r"(bf[nt][1]));
                }
        }

        // c0,c1 -> row gID; c2,c3 -> row gID+8. Cols irrelevant (max over s).
        #pragma unroll
        for (int mt = 0; mt < 4; mt++) {
            float m0 = __int_as_float(0xff800000);
            float m1 = __int_as_float(0xff800000);
            #pragma unroll
            for (int nt = 0; nt < 8; nt++) {
                m0 = fmaxf(m0, fmaxf(acc[mt][nt][0], acc[mt][nt][1]));
                m1 = fmaxf(m1, fmaxf(acc[mt][nt][2], acc[mt][nt][3]));
            }
            runmax[mt][0] = fmaxf(runmax[mt][0], m0);
            runmax[mt][1] = fmaxf(runmax[mt][1], m1);
        }
        __syncthreads();   // buffer reads done before next prefetch overwrites
    }

    // ---- reduce: quad max across tig, publish per (warp_n, row) ----
    float* red = reinterpret_cast<float*>(shb);   // reuse smem: 2*128 floats
    #pragma unroll
    for (int mt = 0; mt < 4; mt++)
        #pragma unroll
        for (int h = 0; h < 2; h++) {
            float m = runmax[mt][h];
            m = fmaxf(m, __shfl_xor_sync(0xffffffffu, m, 1));
            m = fmaxf(m, __shfl_xor_sync(0xffffffffu, m, 2));
            if (tig == 0) {
                int row = warp_m * 64 + mt * 16 + h * 8 + gID;
                red[warp_n * 128 + row] = m;
            }
        }
    __syncthreads();

    // rows wid*32..+31 belong to b_global = mtile*4 + wid; n = lane
    {
        int row = wid * 32 + lane;
        float v = fmaxf(red[row], red[128 + row]);
        #pragma unroll
        for (int off = 16; off > 0; off >>= 1)
            v += __shfl_xor_sync(0xffffffffu, v, off);
        if (lane == 0)
            g_scores[(mtile * 4 + wid) * C + c] = v;
    }
}

// ---------------------------------------------------------------------------
// Kernel 2: normalize, log-softmax, NLL mean. No q reads (g_inv precomputed).
// ---------------------------------------------------------------------------
__global__ void colbert_loss_kernel(const int* __restrict__ offset_p,
                                    float*     __restrict__ out)
{
    __shared__ float losses[B];
    const int tid  = threadIdx.x;
    const int wid  = tid >> 5;
    const int lane = tid & 31;
    const int label_off = offset_p[0];

    #pragma unroll
    for (int r = 0; r < 4; r++) {
        const int b = wid * 4 + r;
        const float inv = g_inv[b];

        float l0 = g_scores[b * C + lane]      * inv;
        float l1 = g_scores[b * C + 32 + lane] * inv;

        float mx = fmaxf(l0, l1);
        #pragma unroll
        for (int o = 16; o > 0; o >>= 1)
            mx = fmaxf(mx, __shfl_xor_sync(0xffffffffu, mx, o));

        float se = expf(l0 - mx) + expf(l1 - mx);
        #pragma unroll
        for (int o = 16; o > 0; o >>= 1)
            se += __shfl_xor_sync(0xffffffffu, se, o);

        const int label = b + label_off;
        const float ll = (label < 32)
                       ? __shfl_sync(0xffffffffu, l0, label)
                       : __shfl_sync(0xffffffffu, l1, label - 32);
        if (lane == 0)
            losses[b] = -(ll - mx - logf(se));
    }
    __syncthreads();

    if (tid < 32) {
        float v = losses[tid] + losses[tid + 32];
        #pragma unroll
        for (int o = 16; o > 0; o >>= 1)
            v += __shfl_xor_sync(0xffffffffu, v, o);
        if (tid == 0) out[0] = v / (float)B;
    }
}

// ---------------------------------------------------------------------------
extern "C" void kernel_launch(void* const* d_in, const int* in_sizes, int n_in,
                              void* d_out, int out_size)
{
    const float* q   = (const float*)d_in[0];
    const float* d   = (const float*)d_in[1];
    const int*   off = (const int*)  d_in[2];
    float*       out = (float*)d_out;

    const size_t smem_bytes = (size_t)(MT * PADB + 2 * NT * PADB)
                              * sizeof(__nv_bfloat16);   // 104448

    cudaFuncSetAttribute(colbert_scores_mma,
                         cudaFuncAttributeMaxDynamicSharedMemorySize,
                         (int)smem_bytes);

    convert_bf16_kernel<<<1024, 256>>>(q, d);
    dim3 grid(16, C);
    colbert_scores_mma<<<grid, 128, smem_bytes>>>();
    colbert_loss_kernel<<<1, 512>>>(off, out);
}